// round 5
// baseline (speedup 1.0000x reference)
#include <cuda_runtime.h>

// LSTM: B=4096, T=512, I=3, H=32, C=3
// One warp processes NB=4 batch elements; lane l owns hidden unit l.
// R4: shuffles eliminated — h broadcast via double-buffered duplicated SMEM,
// x staged pre-duplicated, all gate math on packed fp32x2 FMA.

#define FULL_MASK 0xffffffffu
typedef unsigned long long ull;

constexpr int B_DIM  = 4096;
constexpr int T_DIM  = 512;
constexpr int H_DIM  = 32;
constexpr int NB     = 4;   // batches per warp
constexpr int WARPS  = 4;   // warps per block
constexpr int NTHREADS = WARPS * 32;
constexpr int CHUNK  = 32;  // timesteps of x staged per phase

__device__ __forceinline__ float fast_sigmoid(float x) {
    return __fdividef(1.0f, 1.0f + __expf(-x));
}
__device__ __forceinline__ float fast_tanh(float x) {
    float e = __expf(-2.0f * x);
    return __fdividef(1.0f - e, 1.0f + e);
}
__device__ __forceinline__ ull pack2(float lo, float hi) {
    ull r;
    asm("mov.b64 %0, {%1, %2};"
        : "=l"(r) : "r"(__float_as_uint(lo)), "r"(__float_as_uint(hi)));
    return r;
}
__device__ __forceinline__ void unpack2(ull v, float& lo, float& hi) {
    unsigned int a, b;
    asm("mov.b64 {%0, %1}, %2;" : "=r"(a), "=r"(b) : "l"(v));
    lo = __uint_as_float(a);
    hi = __uint_as_float(b);
}
__device__ __forceinline__ void fma2(ull& acc, ull a, ull b) {
    asm("fma.rn.f32x2 %0, %1, %2, %0;" : "+l"(acc) : "l"(a), "l"(b));
}
__device__ __forceinline__ ull fma2o(ull a, ull b, ull c) {
    ull d;
    asm("fma.rn.f32x2 %0, %1, %2, %3;" : "=l"(d) : "l"(a), "l"(b), "l"(c));
    return d;
}

__global__ void __launch_bounds__(NTHREADS)
lstm_fused_kernel(const float* __restrict__ x,      // (B,T,3)
                  const float* __restrict__ W_ih,   // (128,3)
                  const float* __restrict__ W_hh,   // (128,32)
                  const float* __restrict__ b_ih,   // (128,)
                  const float* __restrict__ b_hh,   // (128,)
                  const float* __restrict__ W_fc,   // (3,32)
                  const float* __restrict__ b_fc,   // (3,)
                  float* __restrict__ out)          // (B,3)
{
    // sW float layout: sW[j*128 + lane*4 + q] = W_hh[(q*32+lane)*32 + j]
    __shared__ float4 sW4[H_DIM * H_DIM];            // 16 KB
    // duplicated h, double-buffered: sh[w][p][j*2+k] : float4 {h,h,h',h'}
    __shared__ float4 sh[WARPS][2][H_DIM * 2];       // 8 KB
    // duplicated x: records of 8 floats {x0,x0,x1,x1,x2,x2,pad,pad}
    __shared__ float sx[WARPS][NB * CHUNK * 8];      // 16 KB

    const int tid  = threadIdx.x;
    const int lane = tid & 31;
    const int warp = tid >> 5;
    const int b0   = (blockIdx.x * WARPS + warp) * NB;

    // ---- stage W_hh (block cooperative) ----
    {
        float* sW = reinterpret_cast<float*>(sW4);
        for (int sidx = tid; sidx < 4 * H_DIM * H_DIM; sidx += NTHREADS) {
            int q  = sidx & 3;
            int ln = (sidx >> 2) & 31;
            int j  = sidx >> 7;
            sW[sidx] = W_hh[(q * 32 + ln) * H_DIM + j];
        }
    }

    // ---- per-lane packed input weights + combined bias ----
    // wp01[k] = {W_ih[lane,k],    W_ih[32+lane,k]}   (gates i,f)
    // wp23[k] = {W_ih[64+lane,k], W_ih[96+lane,k]}   (gates g,o)
    ull wp01[3], wp23[3];
#pragma unroll
    for (int k = 0; k < 3; k++) {
        wp01[k] = pack2(W_ih[(0 * 32 + lane) * 3 + k], W_ih[(1 * 32 + lane) * 3 + k]);
        wp23[k] = pack2(W_ih[(2 * 32 + lane) * 3 + k], W_ih[(3 * 32 + lane) * 3 + k]);
    }
    const ull bias01 = pack2(b_ih[lane]      + b_hh[lane],
                             b_ih[32 + lane] + b_hh[32 + lane]);
    const ull bias23 = pack2(b_ih[64 + lane] + b_hh[64 + lane],
                             b_ih[96 + lane] + b_hh[96 + lane]);
    const float wfc0 = W_fc[0 * H_DIM + lane];
    const float wfc1 = W_fc[1 * H_DIM + lane];
    const float wfc2 = W_fc[2 * H_DIM + lane];

    // init h buffer 0 to zeros (h0 = 0)
    sh[warp][0][lane * 2 + 0] = make_float4(0.f, 0.f, 0.f, 0.f);
    sh[warp][0][lane * 2 + 1] = make_float4(0.f, 0.f, 0.f, 0.f);

    __syncthreads();

    float h[NB], c[NB];
#pragma unroll
    for (int n = 0; n < NB; n++) { h[n] = 0.0f; c[n] = 0.0f; }

    const ulonglong2* sWv = reinterpret_cast<const ulonglong2*>(sW4); // [j*32+lane]
    const float4* xv = reinterpret_cast<const float4*>(x);
    float* sxw = sx[warp];
    int pb = 0;  // read-buffer parity

    for (int tc = 0; tc < T_DIM; tc += CHUNK) {
        // ---- stage x chunk, duplicated: 4 batches * 24 gmem float4 per warp ----
        {
            const int cbase = (tc / CHUNK) * 24;   // = tc*3/4
#pragma unroll
            for (int k = 0; k < 3; k++) {
                int idx = lane + k * 32;           // 0..95
                int n = idx / 24, rem = idx % 24;
                float4 v = xv[(size_t)(b0 + n) * (T_DIM * 3 / 4) + cbase + rem];
                const float* ve = &v.x;
#pragma unroll
                for (int e = 0; e < 4; e++) {
                    int flat = rem * 4 + e;
                    int t = flat / 3, cmp = flat - 3 * t;
                    float* dst = &sxw[(n * CHUNK + t) * 8 + cmp * 2];
                    dst[0] = ve[e];
                    dst[1] = ve[e];
                }
            }
        }
        __syncwarp();

        for (int tt = 0; tt < CHUNK; tt++) {
            // ---- input projection (broadcast duplicated x) ----
            ull acc01[NB], acc23[NB];
#pragma unroll
            for (int n = 0; n < NB; n++) {
                const float* xb = &sxw[(n * CHUNK + tt) * 8];
                ulonglong2 xa = *reinterpret_cast<const ulonglong2*>(xb);      // {x0x0, x1x1}
                ull x22 = *reinterpret_cast<const ull*>(xb + 4);               // {x2x2}
                ull a01 = fma2o(wp01[0], xa.x, bias01);
                ull a23 = fma2o(wp23[0], xa.x, bias23);
                a01 = fma2o(wp01[1], xa.y, a01);
                a23 = fma2o(wp23[1], xa.y, a23);
                a01 = fma2o(wp01[2], x22, a01);
                a23 = fma2o(wp23[2], x22, a23);
                acc01[n] = a01;
                acc23[n] = a23;
            }

            // ---- recurrent matvec: g += W_hh * h (broadcast duplicated h) ----
            const ulonglong2* hbuf =
                reinterpret_cast<const ulonglong2*>(&sh[warp][pb][0]);
#pragma unroll 8
            for (int j = 0; j < H_DIM; j++) {
                ulonglong2 w  = sWv[j * 32 + lane];  // {w_i,w_f} {w_g,w_o}
                ulonglong2 ha = hbuf[j * 2 + 0];     // {h0,h0} {h1,h1}
                ulonglong2 hb = hbuf[j * 2 + 1];     // {h2,h2} {h3,h3}
                fma2(acc01[0], w.x, ha.x); fma2(acc23[0], w.y, ha.x);
                fma2(acc01[1], w.x, ha.y); fma2(acc23[1], w.y, ha.y);
                fma2(acc01[2], w.x, hb.x); fma2(acc23[2], w.y, hb.x);
                fma2(acc01[3], w.x, hb.y); fma2(acc23[3], w.y, hb.y);
            }

            // ---- gates + cell update ----
#pragma unroll
            for (int n = 0; n < NB; n++) {
                float ig, fg, gg, og;
                unpack2(acc01[n], ig, fg);
                unpack2(acc23[n], gg, og);
                ig = fast_sigmoid(ig);
                fg = fast_sigmoid(fg);
                gg = fast_tanh(gg);
                og = fast_sigmoid(og);
                c[n] = fmaf(fg, c[n], ig * gg);
                h[n] = og * fast_tanh(c[n]);
            }

            // ---- publish h (duplicated) to the other buffer ----
            sh[warp][pb ^ 1][lane * 2 + 0] = make_float4(h[0], h[0], h[1], h[1]);
            sh[warp][pb ^ 1][lane * 2 + 1] = make_float4(h[2], h[2], h[3], h[3]);
            __syncwarp();
            pb ^= 1;
        }
    }

    // ---- final FC: out[b,c] = h . W_fc[c,:] + b_fc[c] ----
#pragma unroll
    for (int n = 0; n < NB; n++) {
        float v0 = h[n] * wfc0;
        float v1 = h[n] * wfc1;
        float v2 = h[n] * wfc2;
#pragma unroll
        for (int off = 16; off > 0; off >>= 1) {
            v0 += __shfl_xor_sync(FULL_MASK, v0, off);
            v1 += __shfl_xor_sync(FULL_MASK, v1, off);
            v2 += __shfl_xor_sync(FULL_MASK, v2, off);
        }
        if (lane == 0) {
            out[(b0 + n) * 3 + 0] = v0 + b_fc[0];
            out[(b0 + n) * 3 + 1] = v1 + b_fc[1];
            out[(b0 + n) * 3 + 2] = v2 + b_fc[2];
        }
    }
}

extern "C" void kernel_launch(void* const* d_in, const int* in_sizes, int n_in,
                              void* d_out, int out_size) {
    const float* x    = (const float*)d_in[0];
    const float* W_ih = (const float*)d_in[1];
    const float* W_hh = (const float*)d_in[2];
    const float* b_ih = (const float*)d_in[3];
    const float* b_hh = (const float*)d_in[4];
    const float* W_fc = (const float*)d_in[5];
    const float* b_fc = (const float*)d_in[6];
    float* out = (float*)d_out;

    const int batches_per_block = WARPS * NB;   // 16
    const int grid = B_DIM / batches_per_block; // 256
    lstm_fused_kernel<<<grid, NTHREADS>>>(x, W_ih, W_hh, b_ih, b_hh, W_fc, b_fc, out);
}

// round 6
// speedup vs baseline: 1.2322x; 1.2322x over previous
#include <cuda_runtime.h>

// LSTM: B=4096, T=512, I=3, H=32, C=3
// R5: R3 structure (shuffle-based h broadcast, SMEM weights, fp32x2 FMA)
//     + MUFU.TANH activations + 1-warp blocks (grid=1024) for even SM load.

#define FULL_MASK 0xffffffffu
typedef unsigned long long ull;

constexpr int B_DIM  = 4096;
constexpr int T_DIM  = 512;
constexpr int H_DIM  = 32;
constexpr int NB     = 4;    // batches per warp (= per block)
constexpr int NTHREADS = 32; // one warp per block
constexpr int CHUNK  = 32;   // timesteps of x staged per phase

__device__ __forceinline__ float tanh_fast(float x) {
    float y;
    asm("tanh.approx.f32 %0, %1;" : "=f"(y) : "f"(x));
    return y;
}
__device__ __forceinline__ float sigmoid_fast(float x) {
    return fmaf(0.5f, tanh_fast(0.5f * x), 0.5f);
}
__device__ __forceinline__ ull pack2(float lo, float hi) {
    ull r;
    asm("mov.b64 %0, {%1, %2};"
        : "=l"(r) : "r"(__float_as_uint(lo)), "r"(__float_as_uint(hi)));
    return r;
}
__device__ __forceinline__ void unpack2(ull v, float& lo, float& hi) {
    unsigned int a, b;
    asm("mov.b64 {%0, %1}, %2;" : "=r"(a), "=r"(b) : "l"(v));
    lo = __uint_as_float(a);
    hi = __uint_as_float(b);
}
__device__ __forceinline__ void fma2(ull& acc, ull a, ull b) {
    asm("fma.rn.f32x2 %0, %1, %2, %0;" : "+l"(acc) : "l"(a), "l"(b));
}

__global__ void __launch_bounds__(NTHREADS)
lstm_fused_kernel(const float* __restrict__ x,      // (B,T,3)
                  const float* __restrict__ W_ih,   // (128,3)
                  const float* __restrict__ W_hh,   // (128,32)
                  const float* __restrict__ b_ih,   // (128,)
                  const float* __restrict__ b_hh,   // (128,)
                  const float* __restrict__ W_fc,   // (3,32)
                  const float* __restrict__ b_fc,   // (3,)
                  float* __restrict__ out)          // (B,3)
{
    // sW float layout: sW[j*128 + lane*4 + q] = W_hh[(q*32+lane)*32 + j]
    __shared__ float4 sW4[H_DIM * H_DIM];          // 16 KB
    __shared__ float4 sx4[NB * (CHUNK * 3 / 4)];   // 96 float4 = 1.5 KB

    const int lane = threadIdx.x & 31;
    const int b0   = blockIdx.x * NB;

    // ---- stage W_hh (one warp) ----
    {
        float* sW = reinterpret_cast<float*>(sW4);
        for (int sidx = lane; sidx < 4 * H_DIM * H_DIM; sidx += 32) {
            int q  = sidx & 3;
            int ln = (sidx >> 2) & 31;
            int j  = sidx >> 7;
            sW[sidx] = W_hh[(q * 32 + ln) * H_DIM + j];
        }
    }

    // ---- per-lane input weights, combined bias, fc weights ----
    float wih[4][3];
    float bias[4];
#pragma unroll
    for (int q = 0; q < 4; q++) {
        int row = q * 32 + lane;
        wih[q][0] = W_ih[row * 3 + 0];
        wih[q][1] = W_ih[row * 3 + 1];
        wih[q][2] = W_ih[row * 3 + 2];
        bias[q]   = b_ih[row] + b_hh[row];
    }
    const float wfc0 = W_fc[0 * H_DIM + lane];
    const float wfc1 = W_fc[1 * H_DIM + lane];
    const float wfc2 = W_fc[2 * H_DIM + lane];

    __syncwarp();

    float h[NB], c[NB];
#pragma unroll
    for (int n = 0; n < NB; n++) { h[n] = 0.0f; c[n] = 0.0f; }

    const ulonglong2* sWv = reinterpret_cast<const ulonglong2*>(sW4); // [j*32 + lane]
    const float* sxf = reinterpret_cast<const float*>(sx4);
    const float4* xv = reinterpret_cast<const float4*>(x);

    for (int tc = 0; tc < T_DIM; tc += CHUNK) {
        // ---- stage x chunk: 4 batches * 24 float4 ----
        {
            const int cbase = (tc / CHUNK) * 24;  // = tc*3/4
#pragma unroll
            for (int k = 0; k < 3; k++) {
                int idx = lane + k * 32;          // 0..95
                int n = idx / 24, rem = idx % 24;
                sx4[idx] = xv[(size_t)(b0 + n) * (T_DIM * 3 / 4) + cbase + rem];
            }
        }
        __syncwarp();

        for (int tt = 0; tt < CHUNK; tt++) {
            unsigned long long acc01[NB], acc23[NB];
#pragma unroll
            for (int n = 0; n < NB; n++) {
                float x0 = sxf[n * 96 + tt * 3 + 0];
                float x1 = sxf[n * 96 + tt * 3 + 1];
                float x2 = sxf[n * 96 + tt * 3 + 2];
                float a0 = fmaf(x2, wih[0][2], fmaf(x1, wih[0][1], fmaf(x0, wih[0][0], bias[0])));
                float a1 = fmaf(x2, wih[1][2], fmaf(x1, wih[1][1], fmaf(x0, wih[1][0], bias[1])));
                float a2 = fmaf(x2, wih[2][2], fmaf(x1, wih[2][1], fmaf(x0, wih[2][0], bias[2])));
                float a3 = fmaf(x2, wih[3][2], fmaf(x1, wih[3][1], fmaf(x0, wih[3][0], bias[3])));
                acc01[n] = pack2(a0, a1);
                acc23[n] = pack2(a2, a3);
            }

            // recurrent matvec: g += W_hh * h  (packed gate pairs, h via shuffle)
#pragma unroll
            for (int j = 0; j < H_DIM; j++) {
                ulonglong2 w = sWv[j * 32 + lane]; // {w_i,w_f} {w_g,w_o} for unit `lane`
#pragma unroll
                for (int n = 0; n < NB; n++) {
                    float hj = __shfl_sync(FULL_MASK, h[n], j);
                    ull hjj = pack2(hj, hj);
                    fma2(acc01[n], w.x, hjj);
                    fma2(acc23[n], w.y, hjj);
                }
            }

            // gates + cell update (MUFU.TANH based)
#pragma unroll
            for (int n = 0; n < NB; n++) {
                float ig, fg, gg, og;
                unpack2(acc01[n], ig, fg);
                unpack2(acc23[n], gg, og);
                ig = sigmoid_fast(ig);
                fg = sigmoid_fast(fg);
                gg = tanh_fast(gg);
                og = sigmoid_fast(og);
                c[n] = fmaf(fg, c[n], ig * gg);
                h[n] = og * tanh_fast(c[n]);
            }
        }
        __syncwarp();
    }

    // ---- final FC: out[b,c] = h . W_fc[c,:] + b_fc[c] ----
#pragma unroll
    for (int n = 0; n < NB; n++) {
        float v0 = h[n] * wfc0;
        float v1 = h[n] * wfc1;
        float v2 = h[n] * wfc2;
#pragma unroll
        for (int off = 16; off > 0; off >>= 1) {
            v0 += __shfl_xor_sync(FULL_MASK, v0, off);
            v1 += __shfl_xor_sync(FULL_MASK, v1, off);
            v2 += __shfl_xor_sync(FULL_MASK, v2, off);
        }
        if (lane == 0) {
            out[(b0 + n) * 3 + 0] = v0 + b_fc[0];
            out[(b0 + n) * 3 + 1] = v1 + b_fc[1];
            out[(b0 + n) * 3 + 2] = v2 + b_fc[2];
        }
    }
}

extern "C" void kernel_launch(void* const* d_in, const int* in_sizes, int n_in,
                              void* d_out, int out_size) {
    const float* x    = (const float*)d_in[0];
    const float* W_ih = (const float*)d_in[1];
    const float* W_hh = (const float*)d_in[2];
    const float* b_ih = (const float*)d_in[3];
    const float* b_hh = (const float*)d_in[4];
    const float* W_fc = (const float*)d_in[5];
    const float* b_fc = (const float*)d_in[6];
    float* out = (float*)d_out;

    const int grid = B_DIM / NB;  // 1024 one-warp blocks
    lstm_fused_kernel<<<grid, NTHREADS>>>(x, W_ih, W_hh, b_ih, b_hh, W_fc, b_fc, out);
}

// round 8
// speedup vs baseline: 1.3342x; 1.0827x over previous
#include <cuda_runtime.h>

// LSTM: B=4096, T=512, I=3, H=32, C=3
// R6: W_hh held in registers (packed f32x2 pairs); h broadcast via duplicated
//     SMEM float4 + broadcast LDS.128 (no shuffles, no per-step weight loads);
//     sigmoid 0.5-scale folded into weights; MUFU.TANH activations;
//     1-warp blocks (grid=1024).

#define FULL_MASK 0xffffffffu
typedef unsigned long long ull;

constexpr int B_DIM  = 4096;
constexpr int T_DIM  = 512;
constexpr int H_DIM  = 32;
constexpr int NB     = 4;    // batches per warp (= per block)
constexpr int NTHREADS = 32; // one warp per block
constexpr int CHUNK  = 32;   // timesteps of x staged per phase

__device__ __forceinline__ float tanh_fast(float x) {
    float y;
    asm("tanh.approx.f32 %0, %1;" : "=f"(y) : "f"(x));
    return y;
}
__device__ __forceinline__ ull pack2(float lo, float hi) {
    ull r;
    asm("mov.b64 %0, {%1, %2};"
        : "=l"(r) : "r"(__float_as_uint(lo)), "r"(__float_as_uint(hi)));
    return r;
}
__device__ __forceinline__ void unpack2(ull v, float& lo, float& hi) {
    unsigned int a, b;
    asm("mov.b64 {%0, %1}, %2;" : "=r"(a), "=r"(b) : "l"(v));
    lo = __uint_as_float(a);
    hi = __uint_as_float(b);
}
__device__ __forceinline__ void fma2(ull& acc, ull a, ull b) {
    asm("fma.rn.f32x2 %0, %1, %2, %0;" : "+l"(acc) : "l"(a), "l"(b));
}

__global__ void __launch_bounds__(NTHREADS)
lstm_fused_kernel(const float* __restrict__ x,      // (B,T,3)
                  const float* __restrict__ W_ih,   // (128,3)
                  const float* __restrict__ W_hh,   // (128,32)
                  const float* __restrict__ b_ih,   // (128,)
                  const float* __restrict__ b_hh,   // (128,)
                  const float* __restrict__ W_fc,   // (3,32)
                  const float* __restrict__ b_fc,   // (3,)
                  float* __restrict__ out)          // (B,3)
{
    // staging layout: sW[j*128 + lane*4 + q] = W_hh[(q*32+lane)*32 + j] * scale(q)
    __shared__ float4 sW4[H_DIM * H_DIM];           // 16 KB (used once)
    __shared__ float4 sx4[NB * (CHUNK * 3 / 4)];    // 1.5 KB
    // duplicated h, double-buffered: shb[pb][j][0]={h0,h0,h1,h1}, [1]={h2,h2,h3,h3}
    __shared__ float4 shb[2][H_DIM][2];             // 2 KB

    const int lane = threadIdx.x & 31;
    const int b0   = blockIdx.x * NB;

    // ---- stage W_hh (one warp), scaling gates i,f,o by 0.5 ----
    {
        float* sW = reinterpret_cast<float*>(sW4);
        for (int sidx = lane; sidx < 4 * H_DIM * H_DIM; sidx += 32) {
            int q  = sidx & 3;
            int ln = (sidx >> 2) & 31;
            int j  = sidx >> 7;
            float s = (q == 2) ? 1.0f : 0.5f;
            sW[sidx] = W_hh[(q * 32 + ln) * H_DIM + j] * s;
        }
    }

    // ---- per-lane input weights + combined bias (scaled), fc weights ----
    float wih[4][3];
    float bias[4];
#pragma unroll
    for (int q = 0; q < 4; q++) {
        int row = q * 32 + lane;
        float s = (q == 2) ? 1.0f : 0.5f;
        wih[q][0] = W_ih[row * 3 + 0] * s;
        wih[q][1] = W_ih[row * 3 + 1] * s;
        wih[q][2] = W_ih[row * 3 + 2] * s;
        bias[q]   = (b_ih[row] + b_hh[row]) * s;
    }
    const float wfc0 = W_fc[0 * H_DIM + lane];
    const float wfc1 = W_fc[1 * H_DIM + lane];
    const float wfc2 = W_fc[2 * H_DIM + lane];

    // init h buffer 0 to zeros
    shb[0][lane][0] = make_float4(0.f, 0.f, 0.f, 0.f);
    shb[0][lane][1] = make_float4(0.f, 0.f, 0.f, 0.f);

    __syncwarp();

    // ---- pull W_hh into registers: 64 packed pairs ----
    ull w01[H_DIM], w23[H_DIM];
    {
        const ulonglong2* sWv = reinterpret_cast<const ulonglong2*>(sW4);
#pragma unroll
        for (int j = 0; j < H_DIM; j++) {
            ulonglong2 t = sWv[j * 32 + lane];  // {w_i,w_f} {w_g,w_o} (scaled)
            w01[j] = t.x;
            w23[j] = t.y;
        }
    }

    float h[NB], c[NB];
#pragma unroll
    for (int n = 0; n < NB; n++) { h[n] = 0.0f; c[n] = 0.0f; }

    const float* sxf = reinterpret_cast<const float*>(sx4);
    const float4* xv = reinterpret_cast<const float4*>(x);
    int pb = 0;

    for (int tc = 0; tc < T_DIM; tc += CHUNK) {
        // ---- stage x chunk: 4 batches * 24 float4 ----
        {
            const int cbase = (tc / CHUNK) * 24;  // = tc*3/4
#pragma unroll
            for (int k = 0; k < 3; k++) {
                int idx = lane + k * 32;          // 0..95
                int n = idx / 24, rem = idx % 24;
                sx4[idx] = xv[(size_t)(b0 + n) * (T_DIM * 3 / 4) + cbase + rem];
            }
        }
        __syncwarp();

#pragma unroll 1
        for (int tt = 0; tt < CHUNK; tt++) {
            // ---- input projection (scalar broadcast x, pre-scaled weights) ----
            ull acc01[NB], acc23[NB];
#pragma unroll
            for (int n = 0; n < NB; n++) {
                float x0 = sxf[n * 96 + tt * 3 + 0];
                float x1 = sxf[n * 96 + tt * 3 + 1];
                float x2 = sxf[n * 96 + tt * 3 + 2];
                float a0 = fmaf(x2, wih[0][2], fmaf(x1, wih[0][1], fmaf(x0, wih[0][0], bias[0])));
                float a1 = fmaf(x2, wih[1][2], fmaf(x1, wih[1][1], fmaf(x0, wih[1][0], bias[1])));
                float a2 = fmaf(x2, wih[2][2], fmaf(x1, wih[2][1], fmaf(x0, wih[2][0], bias[2])));
                float a3 = fmaf(x2, wih[3][2], fmaf(x1, wih[3][1], fmaf(x0, wih[3][0], bias[3])));
                acc01[n] = pack2(a0, a1);
                acc23[n] = pack2(a2, a3);
            }

            // ---- recurrent matvec: weights in regs, h via broadcast LDS.128 ----
            {
                const ulonglong2* hb =
                    reinterpret_cast<const ulonglong2*>(&shb[pb][0][0]);
#pragma unroll
                for (int j = 0; j < H_DIM; j++) {
                    ulonglong2 ha = hb[j * 2 + 0];  // {h0,h0} {h1,h1}
                    ulonglong2 hc = hb[j * 2 + 1];  // {h2,h2} {h3,h3}
                    fma2(acc01[0], w01[j], ha.x); fma2(acc23[0], w23[j], ha.x);
                    fma2(acc01[1], w01[j], ha.y); fma2(acc23[1], w23[j], ha.y);
                    fma2(acc01[2], w01[j], hc.x); fma2(acc23[2], w23[j], hc.x);
                    fma2(acc01[3], w01[j], hc.y); fma2(acc23[3], w23[j], hc.y);
                }
            }

            // ---- gates + cell update (i,f,o pre-scaled by 0.5) ----
#pragma unroll
            for (int n = 0; n < NB; n++) {
                float ig, fg, gg, og;
                unpack2(acc01[n], ig, fg);
                unpack2(acc23[n], gg, og);
                ig = fmaf(0.5f, tanh_fast(ig), 0.5f);
                fg = fmaf(0.5f, tanh_fast(fg), 0.5f);
                gg = tanh_fast(gg);
                og = fmaf(0.5f, tanh_fast(og), 0.5f);
                c[n] = fmaf(fg, c[n], ig * gg);
                h[n] = og * tanh_fast(c[n]);
            }

            // ---- publish duplicated h to the other buffer ----
            shb[pb ^ 1][lane][0] = make_float4(h[0], h[0], h[1], h[1]);
            shb[pb ^ 1][lane][1] = make_float4(h[2], h[2], h[3], h[3]);
            __syncwarp();
            pb ^= 1;
        }
    }

    // ---- final FC: out[b,c] = h . W_fc[c,:] + b_fc[c] ----
#pragma unroll
    for (int n = 0; n < NB; n++) {
        float v0 = h[n] * wfc0;
        float v1 = h[n] * wfc1;
        float v2 = h[n] * wfc2;
#pragma unroll
        for (int off = 16; off > 0; off >>= 1) {
            v0 += __shfl_xor_sync(FULL_MASK, v0, off);
            v1 += __shfl_xor_sync(FULL_MASK, v1, off);
            v2 += __shfl_xor_sync(FULL_MASK, v2, off);
        }
        if (lane == 0) {
            out[(b0 + n) * 3 + 0] = v0 + b_fc[0];
            out[(b0 + n) * 3 + 1] = v1 + b_fc[1];
            out[(b0 + n) * 3 + 2] = v2 + b_fc[2];
        }
    }
}

extern "C" void kernel_launch(void* const* d_in, const int* in_sizes, int n_in,
                              void* d_out, int out_size) {
    const float* x    = (const float*)d_in[0];
    const float* W_ih = (const float*)d_in[1];
    const float* W_hh = (const float*)d_in[2];
    const float* b_ih = (const float*)d_in[3];
    const float* b_hh = (const float*)d_in[4];
    const float* W_fc = (const float*)d_in[5];
    const float* b_fc = (const float*)d_in[6];
    float* out = (float*)d_out;

    const int grid = B_DIM / NB;  // 1024 one-warp blocks
    lstm_fused_kernel<<<grid, NTHREADS>>>(x, W_ih, W_hh, b_ih, b_hh, W_fc, b_fc, out);
}